// round 1
// baseline (speedup 1.0000x reference)
#include <cuda_runtime.h>
#include <math.h>

#define BN 1024
#define DN 128
#define HN 128
#define ROWS 8
#define LN_EPS 1e-5f

// scratch for diffs_mean [B, D]
__device__ float g_dm[BN * DN];

// ===========================================================================
// K1: per-column mean |x_i - x_j| via sort + prefix-sum closed form.
// One block per column d (128 blocks), 256 threads, 1024 elements in shared.
// ===========================================================================
__global__ __launch_bounds__(256) void col_absdiff_mean_kernel(
    const float* __restrict__ x, float* __restrict__ dm)
{
    __shared__ float sv[BN];
    __shared__ int   si[BN];
    __shared__ float cs[256];

    const int d = blockIdx.x;
    const int t = threadIdx.x;

    // strided column gather
    #pragma unroll
    for (int w = 0; w < 4; w++) {
        int i = t + w * 256;
        sv[i] = x[i * DN + d];
        si[i] = i;
    }
    __syncthreads();

    // bitonic sort ascending (value, index) pairs
    for (int k = 2; k <= BN; k <<= 1) {
        for (int j = k >> 1; j > 0; j >>= 1) {
            #pragma unroll
            for (int w = 0; w < 4; w++) {
                int i = t + w * 256;
                int ixj = i ^ j;
                if (ixj > i) {
                    float a = sv[i];
                    float b = sv[ixj];
                    bool up = ((i & k) == 0);
                    if ((a > b) == up) {
                        sv[i] = b; sv[ixj] = a;
                        int ia = si[i]; si[i] = si[ixj]; si[ixj] = ia;
                    }
                }
            }
            __syncthreads();
        }
    }

    // inclusive prefix sums: 4-element local chunks + Hillis-Steele over 256
    float e0 = sv[4 * t];
    float l0 = e0;
    float l1 = l0 + sv[4 * t + 1];
    float l2 = l1 + sv[4 * t + 2];
    float l3 = l2 + sv[4 * t + 3];
    cs[t] = l3;
    __syncthreads();
    for (int off = 1; off < 256; off <<= 1) {
        float v = (t >= off) ? cs[t - off] : 0.0f;
        __syncthreads();
        cs[t] += v;
        __syncthreads();
    }
    const float S = cs[255];
    const float chunk_excl = cs[t] - l3;

    float linc[4] = { l0, l1, l2, l3 };
    #pragma unroll
    for (int e = 0; e < 4; e++) {
        int p = 4 * t + e;
        float v = sv[p];
        float Pinc = chunk_excl + linc[e];
        // sum_j |v_p - v_j| for sorted ascending array
        float s = v * (float)(2 * (p + 1) - BN) + S - 2.0f * Pinc;
        dm[si[p] * DN + d] = s * (1.0f / (float)BN);
    }
}

// ===========================================================================
// K3: fused  d_mean = dm @ Wd^T + bd ; tau ; h = relu((d/tau) @ Wa^T + ba) ;
//            y = h + x @ Wr^T + br ; LayerNorm(y) * gamma + beta
// 128 blocks x 8 rows, 256 threads (two k-halves of 64 each).
// All three W matrices transposed into padded shared [k][col] (stride 129).
// ===========================================================================
__device__ __forceinline__ void matvec_half8(
    const float* __restrict__ Ws,   // shared, [128][129] transposed
    const float* __restrict__ in,   // shared, [k][8] row-batched input
    int col, int half, float acc[8])
{
    const float* Wp = Ws + (half * 64) * 129 + col;
    const float* ip = in + (half * 64) * 8;
    #pragma unroll 8
    for (int k = 0; k < 64; k++) {
        float w = Wp[k * 129];
        float4 a0 = *(const float4*)(ip + k * 8);
        float4 a1 = *(const float4*)(ip + k * 8 + 4);
        acc[0] = fmaf(a0.x, w, acc[0]);
        acc[1] = fmaf(a0.y, w, acc[1]);
        acc[2] = fmaf(a0.z, w, acc[2]);
        acc[3] = fmaf(a0.w, w, acc[3]);
        acc[4] = fmaf(a1.x, w, acc[4]);
        acc[5] = fmaf(a1.y, w, acc[5]);
        acc[6] = fmaf(a1.z, w, acc[6]);
        acc[7] = fmaf(a1.w, w, acc[7]);
    }
}

__global__ __launch_bounds__(256) void fused_tail_kernel(
    const float* __restrict__ x,
    const float* __restrict__ Wd, const float* __restrict__ bd,
    const float* __restrict__ Wt, const float* __restrict__ bt,
    const float* __restrict__ Wa, const float* __restrict__ ba,
    const float* __restrict__ Wr, const float* __restrict__ br,
    const float* __restrict__ gamma, const float* __restrict__ beta,
    const float* __restrict__ dm,
    float* __restrict__ out)
{
    extern __shared__ float sm[];
    float* Wd_s = sm;                       // 128*129
    float* Wa_s = Wd_s + 128 * 129;
    float* Wr_s = Wa_s + 128 * 129;
    float* Wt_s = Wr_s + 128 * 129;         // 128
    float* bd_s = Wt_s + 128;
    float* ba_s = bd_s + 128;
    float* br_s = ba_s + 128;
    float* g_s  = br_s + 128;
    float* be_s = g_s + 128;
    float* xs   = be_s + 128;               // [k][8] 1024
    float* dms  = xs + 1024;                // 1024
    float* hms  = dms + 1024;               // 1024
    float* part = hms + 1024;               // 1024 (half-1 partials)
    float* redS = part + 1024;              // 32
    float* redQ = redS + 32;                // 32
    float* tau_s = redQ + 32;               // 8
    float* musig = tau_s + 8;               // 16

    const int t = threadIdx.x;
    const int col = t & 127;
    const int half = t >> 7;
    const int lane = t & 31;
    const int warp = t >> 5;
    const int i0 = blockIdx.x * ROWS;

    // load weights transposed: Ws[c*129 + r] = W[r*128 + c]
    for (int e = t; e < 128 * 128; e += 256) {
        int r = e >> 7, c = e & 127;
        float vd = Wd[e], va = Wa[e], vr = Wr[e];
        Wd_s[c * 129 + r] = vd;
        Wa_s[c * 129 + r] = va;
        Wr_s[c * 129 + r] = vr;
    }
    if (t < 128) {
        Wt_s[t] = Wt[t]; bd_s[t] = bd[t]; ba_s[t] = ba[t];
        br_s[t] = br[t]; g_s[t] = gamma[t]; be_s[t] = beta[t];
    }
    // load 8 rows of x and dm, batched layout [k][r]
    for (int e = t; e < 1024; e += 256) {
        int k = e & 127, r = e >> 7;
        xs[k * 8 + r]  = x[(i0 + r) * DN + k];
        dms[k * 8 + r] = dm[(i0 + r) * DN + k];
    }
    __syncthreads();

    // --- tau per row (threads 0..127) ---
    if (half == 0) {
        float4 xa = *(const float4*)(xs + t * 8);
        float4 xb = *(const float4*)(xs + t * 8 + 4);
        float wt = Wt_s[t];
        float pr[8] = { xa.x * wt, xa.y * wt, xa.z * wt, xa.w * wt,
                        xb.x * wt, xb.y * wt, xb.z * wt, xb.w * wt };
        #pragma unroll
        for (int r = 0; r < 8; r++) {
            float v = pr[r];
            #pragma unroll
            for (int o = 16; o; o >>= 1) v += __shfl_xor_sync(0xffffffffu, v, o);
            if (lane == 0) redS[warp * 8 + r] = v;
        }
    }
    __syncthreads();
    if (t < 8) {
        float z = redS[t] + redS[8 + t] + redS[16 + t] + redS[24 + t] + bt[0];
        float sp = fmaxf(z, 0.0f) + log1pf(expf(-fabsf(z)));   // stable softplus
        tau_s[t] = fmaxf(sp, 0.01f) + 1.0f;
    }
    __syncthreads();

    float acc[8];

    // --- matvec 1: d_mean = dm @ Wd^T ---
    #pragma unroll
    for (int r = 0; r < 8; r++) acc[r] = 0.0f;
    matvec_half8(Wd_s, dms, col, half, acc);
    if (half == 1) {
        #pragma unroll
        for (int r = 0; r < 8; r++) part[col * 8 + r] = acc[r];
    }
    __syncthreads();
    if (half == 0) {
        float bdv = bd_s[col];
        #pragma unroll
        for (int r = 0; r < 8; r++)
            hms[col * 8 + r] = (acc[r] + part[col * 8 + r] + bdv) / tau_s[r];
    }
    __syncthreads();

    // --- matvec 2: h = relu(hm @ Wa^T + ba) ---
    #pragma unroll
    for (int r = 0; r < 8; r++) acc[r] = 0.0f;
    matvec_half8(Wa_s, hms, col, half, acc);
    if (half == 1) {
        #pragma unroll
        for (int r = 0; r < 8; r++) part[col * 8 + r] = acc[r];
    }
    __syncthreads();
    float hreg[8];
    if (half == 0) {
        float bav = ba_s[col];
        #pragma unroll
        for (int r = 0; r < 8; r++)
            hreg[r] = fmaxf(acc[r] + part[col * 8 + r] + bav, 0.0f);
    }
    __syncthreads();   // protect 'part' reuse

    // --- matvec 3: y = h + x @ Wr^T + br ---
    #pragma unroll
    for (int r = 0; r < 8; r++) acc[r] = 0.0f;
    matvec_half8(Wr_s, xs, col, half, acc);
    if (half == 1) {
        #pragma unroll
        for (int r = 0; r < 8; r++) part[col * 8 + r] = acc[r];
    }
    __syncthreads();

    float yreg[8];
    if (half == 0) {
        float brv = br_s[col];
        #pragma unroll
        for (int r = 0; r < 8; r++)
            yreg[r] = hreg[r] + acc[r] + part[col * 8 + r] + brv;
        // per-row reductions for LayerNorm
        #pragma unroll
        for (int r = 0; r < 8; r++) {
            float s = yreg[r];
            float q = yreg[r] * yreg[r];
            #pragma unroll
            for (int o = 16; o; o >>= 1) {
                s += __shfl_xor_sync(0xffffffffu, s, o);
                q += __shfl_xor_sync(0xffffffffu, q, o);
            }
            if (lane == 0) { redS[warp * 8 + r] = s; redQ[warp * 8 + r] = q; }
        }
    }
    __syncthreads();
    if (t < 8) {
        float s = redS[t] + redS[8 + t] + redS[16 + t] + redS[24 + t];
        float q = redQ[t] + redQ[8 + t] + redQ[16 + t] + redQ[24 + t];
        float mu = s * (1.0f / 128.0f);
        float var = q * (1.0f / 128.0f) - mu * mu;
        musig[t * 2]     = mu;
        musig[t * 2 + 1] = rsqrtf(var + LN_EPS);
    }
    __syncthreads();
    if (half == 0) {
        float gv = g_s[col], bv = be_s[col];
        #pragma unroll
        for (int r = 0; r < 8; r++) {
            float o = (yreg[r] - musig[r * 2]) * musig[r * 2 + 1] * gv + bv;
            out[(i0 + r) * HN + col] = o;
        }
    }
}

// ===========================================================================
extern "C" void kernel_launch(void* const* d_in, const int* in_sizes, int n_in,
                              void* d_out, int out_size)
{
    const float* x     = (const float*)d_in[0];
    const float* Wd    = (const float*)d_in[1];
    const float* bd    = (const float*)d_in[2];
    const float* Wt    = (const float*)d_in[3];
    const float* bt    = (const float*)d_in[4];
    const float* Wa    = (const float*)d_in[5];
    const float* ba    = (const float*)d_in[6];
    const float* Wr    = (const float*)d_in[7];
    const float* br    = (const float*)d_in[8];
    const float* gamma = (const float*)d_in[9];
    const float* beta  = (const float*)d_in[10];
    float* out = (float*)d_out;

    float* dm = nullptr;
    cudaGetSymbolAddress((void**)&dm, g_dm);

    // K1: diffs_mean
    col_absdiff_mean_kernel<<<DN, 256>>>(x, dm);

    // K3: fused tail
    const size_t smem = (size_t)(3 * 128 * 129 + 6 * 128 + 4 * 1024 + 32 + 32 + 8 + 16)
                        * sizeof(float);
    static bool attr_set = false;
    if (!attr_set) {
        cudaFuncSetAttribute(fused_tail_kernel,
                             cudaFuncAttributeMaxDynamicSharedMemorySize, (int)smem);
        attr_set = true;
    }
    fused_tail_kernel<<<BN / ROWS, 256, smem>>>(
        x, Wd, bd, Wt, bt, Wa, ba, Wr, br, gamma, beta, dm, out);
}

// round 2
// speedup vs baseline: 1.5750x; 1.5750x over previous
#include <cuda_runtime.h>
#include <math.h>

#define BN 1024
#define DN 128
#define HN 128
#define ROWS 8
#define LN_EPS 1e-5f

// scratch for diffs_mean [B, D]
__device__ float g_dm[BN * DN];

// ===========================================================================
// K1: per-column mean |x_i - x_j| via sort + prefix-sum closed form.
// One block per column d (128 blocks), 512 threads.
// Keys packed (order-preserving float encoding << 32 | index) in u64.
// ===========================================================================
__global__ __launch_bounds__(512) void col_absdiff_mean_kernel(
    const float* __restrict__ x, float* __restrict__ dm)
{
    __shared__ unsigned long long sk[BN];
    __shared__ float wsum[16];

    const int d = blockIdx.x;
    const int t = threadIdx.x;
    const int lane = t & 31;
    const int wid = t >> 5;

    #pragma unroll
    for (int w = 0; w < 2; w++) {
        int i = t + w * 512;
        unsigned u = __float_as_uint(x[i * DN + d]);
        u ^= (u & 0x80000000u) ? 0xFFFFFFFFu : 0x80000000u;
        sk[i] = ((unsigned long long)u << 32) | (unsigned)i;
    }
    __syncthreads();

    // bitonic sort ascending, 512 compare-exchanges per stage (1/thread)
    for (int k = 2; k <= BN; k <<= 1) {
        for (int j = k >> 1; j > 0; j >>= 1) {
            int i = ((t & ~(j - 1)) << 1) | (t & (j - 1));
            int ixj = i | j;
            unsigned long long a = sk[i];
            unsigned long long b = sk[ixj];
            bool up = ((i & k) == 0);
            if ((a > b) == up) { sk[i] = b; sk[ixj] = a; }
            __syncthreads();
        }
    }

    // decode my two sorted elements (positions 2t, 2t+1)
    unsigned long long k0 = sk[2 * t];
    unsigned long long k1 = sk[2 * t + 1];
    unsigned u0 = (unsigned)(k0 >> 32);
    unsigned u1 = (unsigned)(k1 >> 32);
    u0 ^= (u0 & 0x80000000u) ? 0x80000000u : 0xFFFFFFFFu;
    u1 ^= (u1 & 0x80000000u) ? 0x80000000u : 0xFFFFFFFFu;
    float v0 = __uint_as_float(u0);
    float v1 = __uint_as_float(u1);
    unsigned idx0 = (unsigned)k0;
    unsigned idx1 = (unsigned)k1;

    // inclusive scan of 512 chunk sums (chunk = 2 elements) via shfl
    float l0 = v0;
    float l1 = v0 + v1;
    float s = l1;
    #pragma unroll
    for (int o = 1; o < 32; o <<= 1) {
        float n = __shfl_up_sync(0xffffffffu, s, o);
        if (lane >= o) s += n;
    }
    if (lane == 31) wsum[wid] = s;
    __syncthreads();
    if (t < 16) {
        float v = wsum[t];
        #pragma unroll
        for (int o = 1; o < 16; o <<= 1) {
            float n = __shfl_up_sync(0x0000ffffu, v, o);
            if (t >= o) v += n;
        }
        wsum[t] = v;
    }
    __syncthreads();
    const float S = wsum[15];
    const float wexcl = (wid == 0) ? 0.0f : wsum[wid - 1];
    const float inc1 = s + wexcl;          // inclusive prefix through pos 2t+1
    const float inc0 = inc1 - l1 + l0;     // inclusive prefix through pos 2t

    // sum_j |v_p - v_j| = v_p*(2(p+1)-B) + S - 2*Pinc(p)
    int p0 = 2 * t;
    float out0 = v0 * (float)(2 * (p0 + 1) - BN) + S - 2.0f * inc0;
    float out1 = v1 * (float)(2 * (p0 + 2) - BN) + S - 2.0f * inc1;
    dm[idx0 * DN + d] = out0 * (1.0f / (float)BN);
    dm[idx1 * DN + d] = out1 * (1.0f / (float)BN);
}

// ===========================================================================
// K3: fused tail. 128 blocks x 8 rows, 512 threads.
// col = t & 127, quarter q = t >> 7 (32 k-values each).
// Weights in shared row-major [h][129] (pad -> conflict-free LDS).
// Accumulation in packed f32x2 (FFMA2) — 4 b64 accs cover 8 rows.
// ===========================================================================
__device__ __forceinline__ unsigned long long fma2(
    unsigned long long a, unsigned long long b, unsigned long long c)
{
    unsigned long long d;
    asm("fma.rn.f32x2 %0, %1, %2, %3;" : "=l"(d) : "l"(a), "l"(b), "l"(c));
    return d;
}

__device__ __forceinline__ void mv32(
    const float* __restrict__ Wrow,     // shared: Ws + col*129 + q*32
    const float* __restrict__ ip,       // shared: in + q*256  ([k][8])
    unsigned long long acc[4])
{
    #pragma unroll 8
    for (int k = 0; k < 32; k++) {
        unsigned long long w2;
        asm("mov.b64 %0, {%1, %1};" : "=l"(w2) : "r"(__float_as_uint(Wrow[k])));
        const ulonglong2* p = (const ulonglong2*)(ip + k * 8);
        ulonglong2 a0 = p[0];
        ulonglong2 a1 = p[1];
        acc[0] = fma2(a0.x, w2, acc[0]);
        acc[1] = fma2(a0.y, w2, acc[1]);
        acc[2] = fma2(a1.x, w2, acc[2]);
        acc[3] = fma2(a1.y, w2, acc[3]);
    }
}

// float-offset layout of dynamic shared
#define OFF_WD   0
#define OFF_WA   16512
#define OFF_WR   33024
#define OFF_XS   49536
#define OFF_DS   50560
#define OFF_PART 51584          /* 3 * 1024 */
#define OFF_WT   54656
#define OFF_BD   54784
#define OFF_BA   54912
#define OFF_BR   55040
#define OFF_G    55168
#define OFF_BE   55296
#define OFF_RS   55424          /* 32 */
#define OFF_RQ   55456          /* 32 */
#define OFF_TAU  55488          /* 8  */
#define OFF_MS   55496          /* 16 */
#define SMEM_FLOATS 55512

__global__ __launch_bounds__(512) void fused_tail_kernel(
    const float* __restrict__ x,
    const float* __restrict__ Wd, const float* __restrict__ bd,
    const float* __restrict__ Wt, const float* __restrict__ bt,
    const float* __restrict__ Wa, const float* __restrict__ ba,
    const float* __restrict__ Wr, const float* __restrict__ br,
    const float* __restrict__ gamma, const float* __restrict__ beta,
    const float* __restrict__ dm,
    float* __restrict__ out)
{
    extern __shared__ float sm[];
    float* Wd_s = sm + OFF_WD;
    float* Wa_s = sm + OFF_WA;
    float* Wr_s = sm + OFF_WR;
    float* xs   = sm + OFF_XS;     // [k][8]
    float* ds   = sm + OFF_DS;     // [k][8]  dm, later h_mean
    float* part = sm + OFF_PART;   // [3][128*8]
    float* redS = sm + OFF_RS;
    float* redQ = sm + OFF_RQ;
    float* tau_s = sm + OFF_TAU;
    float* musig = sm + OFF_MS;

    const int t = threadIdx.x;
    const int col = t & 127;
    const int q = t >> 7;
    const int lane = t & 31;
    const int i0 = blockIdx.x * ROWS;

    // ---- load weights row-major padded [h][129]: coalesced LDG, CF STS ----
    #pragma unroll
    for (int it = 0; it < 32; it++) {
        int e = t + it * 512;
        int r = e >> 7, c = e & 127;
        int o = r * 129 + c;
        Wd_s[o] = Wd[e];
        Wa_s[o] = Wa[e];
        Wr_s[o] = Wr[e];
    }
    if (t < 128) {
        sm[OFF_WT + t] = Wt[t];
        sm[OFF_BD + t] = bd[t];
        sm[OFF_BA + t] = ba[t];
        sm[OFF_BR + t] = br[t];
        sm[OFF_G  + t] = gamma[t];
        sm[OFF_BE + t] = beta[t];
    }
    // ---- load 8 rows of x and dm, batched [k][8] ----
    #pragma unroll
    for (int it = 0; it < 2; it++) {
        int e = t + it * 512;
        int k = e & 127, r = e >> 7;
        xs[k * 8 + r] = x[(i0 + r) * DN + k];
        ds[k * 8 + r] = dm[(i0 + r) * DN + k];
    }
    __syncthreads();

    // ---- tau per row (threads 0..127, k across threads) ----
    if (t < 128) {
        float wt = sm[OFF_WT + t];
        #pragma unroll
        for (int r = 0; r < 8; r++) {
            float v = xs[t * 8 + r] * wt;
            #pragma unroll
            for (int o = 16; o; o >>= 1) v += __shfl_xor_sync(0xffffffffu, v, o);
            if (lane == 0) redS[(t >> 5) * 8 + r] = v;
        }
    }
    __syncthreads();
    if (t < 8) {
        float z = redS[t] + redS[8 + t] + redS[16 + t] + redS[24 + t] + bt[0];
        float sp = fmaxf(z, 0.0f) + log1pf(expf(-fabsf(z)));
        tau_s[t] = fmaxf(sp, 0.01f) + 1.0f;
    }
    __syncthreads();

    __align__(16) float accf[8];
    unsigned long long* acc = reinterpret_cast<unsigned long long*>(accf);

    // ================= matvec 1: d_mean = ds @ Wd^T =================
    #pragma unroll
    for (int h = 0; h < 4; h++) acc[h] = 0ull;
    mv32(Wd_s + col * 129 + q * 32, ds + q * 256, acc);
    if (q != 0) {
        float4* pp = (float4*)(part + (q - 1) * 1024 + col * 8);
        pp[0] = *(float4*)(accf);
        pp[1] = *(float4*)(accf + 4);
    }
    __syncthreads();
    if (q == 0) {
        float bdv = sm[OFF_BD + col];
        const float* p0 = part + col * 8;
        #pragma unroll
        for (int r = 0; r < 8; r++) {
            float v = accf[r] + p0[r] + p0[1024 + r] + p0[2048 + r] + bdv;
            ds[col * 8 + r] = v / tau_s[r];   // overwrite ds with h_mean
        }
    }
    __syncthreads();

    // ================= matvec 2: h = relu(hm @ Wa^T + ba) =================
    #pragma unroll
    for (int h = 0; h < 4; h++) acc[h] = 0ull;
    mv32(Wa_s + col * 129 + q * 32, ds + q * 256, acc);
    if (q != 0) {
        float4* pp = (float4*)(part + (q - 1) * 1024 + col * 8);
        pp[0] = *(float4*)(accf);
        pp[1] = *(float4*)(accf + 4);
    }
    __syncthreads();
    float hreg[8];
    if (q == 0) {
        float bav = sm[OFF_BA + col];
        const float* p0 = part + col * 8;
        #pragma unroll
        for (int r = 0; r < 8; r++)
            hreg[r] = fmaxf(accf[r] + p0[r] + p0[1024 + r] + p0[2048 + r] + bav, 0.0f);
    }
    __syncthreads();   // protect part reuse

    // ================= matvec 3: y = h + x @ Wr^T + br =================
    #pragma unroll
    for (int h = 0; h < 4; h++) acc[h] = 0ull;
    mv32(Wr_s + col * 129 + q * 32, xs + q * 256, acc);
    if (q != 0) {
        float4* pp = (float4*)(part + (q - 1) * 1024 + col * 8);
        pp[0] = *(float4*)(accf);
        pp[1] = *(float4*)(accf + 4);
    }
    __syncthreads();

    float yreg[8];
    if (q == 0) {
        float brv = sm[OFF_BR + col];
        const float* p0 = part + col * 8;
        #pragma unroll
        for (int r = 0; r < 8; r++)
            yreg[r] = hreg[r] + accf[r] + p0[r] + p0[1024 + r] + p0[2048 + r] + brv;
        #pragma unroll
        for (int r = 0; r < 8; r++) {
            float s = yreg[r];
            float qq = yreg[r] * yreg[r];
            #pragma unroll
            for (int o = 16; o; o >>= 1) {
                s  += __shfl_xor_sync(0xffffffffu, s, o);
                qq += __shfl_xor_sync(0xffffffffu, qq, o);
            }
            if (lane == 0) { redS[(t >> 5) * 8 + r] = s; redQ[(t >> 5) * 8 + r] = qq; }
        }
    }
    __syncthreads();
    if (t < 8) {
        float s = redS[t] + redS[8 + t] + redS[16 + t] + redS[24 + t];
        float qq = redQ[t] + redQ[8 + t] + redQ[16 + t] + redQ[24 + t];
        float mu = s * (1.0f / 128.0f);
        float var = qq * (1.0f / 128.0f) - mu * mu;
        musig[t * 2] = mu;
        musig[t * 2 + 1] = rsqrtf(var + LN_EPS);
    }
    __syncthreads();
    if (q == 0) {
        float gv = sm[OFF_G + col], bv = sm[OFF_BE + col];
        #pragma unroll
        for (int r = 0; r < 8; r++) {
            float o = (yreg[r] - musig[r * 2]) * musig[r * 2 + 1] * gv + bv;
            out[(i0 + r) * HN + col] = o;
        }
    }
}

// ===========================================================================
extern "C" void kernel_launch(void* const* d_in, const int* in_sizes, int n_in,
                              void* d_out, int out_size)
{
    const float* x     = (const float*)d_in[0];
    const float* Wd    = (const float*)d_in[1];
    const float* bd    = (const float*)d_in[2];
    const float* Wt    = (const float*)d_in[3];
    const float* bt    = (const float*)d_in[4];
    const float* Wa    = (const float*)d_in[5];
    const float* ba    = (const float*)d_in[6];
    const float* Wr    = (const float*)d_in[7];
    const float* br    = (const float*)d_in[8];
    const float* gamma = (const float*)d_in[9];
    const float* beta  = (const float*)d_in[10];
    float* out = (float*)d_out;

    float* dm = nullptr;
    cudaGetSymbolAddress((void**)&dm, g_dm);

    col_absdiff_mean_kernel<<<DN, 512>>>(x, dm);

    const size_t smem = (size_t)SMEM_FLOATS * sizeof(float);
    cudaFuncSetAttribute(fused_tail_kernel,
                         cudaFuncAttributeMaxDynamicSharedMemorySize, (int)smem);
    fused_tail_kernel<<<BN / ROWS, 512, smem>>>(
        x, Wd, bd, Wt, bt, Wa, ba, Wr, br, gamma, beta, dm, out);
}